// round 13
// baseline (speedup 1.0000x reference)
#include <cuda_runtime.h>
#include <cuda_bf16.h>
#include <cstdint>

#define CC      2048
#define HW      49
#define SIDE    7
#define CGROUPS 8
#define NTHR    512
#define SPLIT   16
#define CHC     (CC / SPLIT)      // 128 channels per CTA
#define NMAX    256

// scratch: [u][p][5] = {sum, a0, a1, d0, d1}
__device__ float g_scratch[NMAX * SPLIT * HW * 5];

// ---------------- K1: streaming partial, packed f32x2 FMAs ----------------
__global__ __launch_bounds__(NTHR, 3)
void rpcp_partial_kernel(const float* __restrict__ x,
                         const float* __restrict__ Wlin,
                         float* __restrict__ scratch)
{
    // per channel: {W1_0, W1_1, W2_0, W2_1} -> two packed f32x2 pairs
    __shared__ alignas(16) float4 wsh[CHC];    // 2 KB
    __shared__ float acc[CGROUPS][HW][5];

    const int tid = threadIdx.x;
    const int u   = blockIdx.x;                // unit id
    const int n   = u >> 4;                    // SPLIT = 16
    const int sp  = u & 15;
    const int c0  = sp * CHC;

    for (int c = tid; c < CHC; c += NTHR) {
        const int cc = c0 + c;
        wsh[c] = make_float4(Wlin[cc],             // W1_0
                             Wlin[2 * CC + cc],    // W1_1
                             Wlin[CC + cc],        // W2_0
                             Wlin[3 * CC + cc]);   // W2_1
    }
    __syncthreads();

    const int p  = tid & 63;     // 0..48 active
    const int cg = tid >> 6;     // 0..7

    if (p < HW) {
        float    s    = 0.f;
        uint64_t accA = 0ull;    // packed {a0, a1}
        uint64_t accD = 0ull;    // packed {d0, d1}

        const float* xp = x + (size_t)n * CC * HW + (size_t)c0 * HW + p;
        const ulonglong2* w64 = reinterpret_cast<const ulonglong2*>(wsh);

        #pragma unroll 4
        for (int c = cg; c < CHC; c += CGROUPS) {   // exactly 16 iterations
            const float v = __ldg(xp + c * HW);     // coalesced across lanes
            const ulonglong2 w = w64[c];            // LDS.128 broadcast:
                                                    // w.x={W1_0,W1_1}, w.y={W2_0,W2_1}
            uint64_t vv;
            const uint32_t vu = __float_as_uint(v);
            asm("mov.b64 %0, {%1, %2};" : "=l"(vv) : "r"(vu), "r"(vu));

            s += v;
            asm("fma.rn.f32x2 %0, %1, %2, %0;" : "+l"(accA) : "l"(vv), "l"(w.x));
            asm("fma.rn.f32x2 %0, %1, %2, %0;" : "+l"(accD) : "l"(vv), "l"(w.y));
        }

        uint32_t a0u, a1u, d0u, d1u;
        asm("mov.b64 {%0, %1}, %2;" : "=r"(a0u), "=r"(a1u) : "l"(accA));
        asm("mov.b64 {%0, %1}, %2;" : "=r"(d0u), "=r"(d1u) : "l"(accD));

        acc[cg][p][0] = s;
        acc[cg][p][1] = __uint_as_float(a0u);
        acc[cg][p][2] = __uint_as_float(a1u);
        acc[cg][p][3] = __uint_as_float(d0u);
        acc[cg][p][4] = __uint_as_float(d1u);
    }
    __syncthreads();

    if (tid < HW * 5) {
        const int pp = tid / 5, k = tid % 5;
        float t = 0.f;
        #pragma unroll
        for (int g = 0; g < CGROUPS; g++) t += acc[g][pp][k];
        scratch[(u * HW + pp) * 5 + k] = t;
    }
}

// ---------------- K2: per-image reduce + epilogue (scratch-only) ----------------
__global__ __launch_bounds__(256, 4)
void rpcp_final_kernel(const float* __restrict__ scratch,
                       const float* __restrict__ bias,
                       float* __restrict__ out)
{
    __shared__ float fin[HW][5];   // {sum, a0, a1, d0, d1}
    __shared__ float gaps[HW];
    __shared__ float dls[HW];
    __shared__ float s_gmean;
    __shared__ int   s_idx;

    const int n   = blockIdx.x;
    const int tid = threadIdx.x;

    if (tid < HW * 5) {
        const int pp = tid / 5, k = tid % 5;
        float t = 0.f;
        #pragma unroll
        for (int g = 0; g < SPLIT; g++)
            t += scratch[(((n << 4) + g) * HW + pp) * 5 + k];
        fin[pp][k] = t;
    }
    __syncthreads();

    // warp argmax over channel-sum (first occurrence on ties)
    if (tid < 32) {
        float v  = fin[tid][0];
        int   bi = tid;
        if (tid + 32 < HW) {
            float v2 = fin[tid + 32][0];
            if (v2 > v) { v = v2; bi = tid + 32; }
        }
        #pragma unroll
        for (int off = 16; off > 0; off >>= 1) {
            float ov = __shfl_down_sync(0xffffffffu, v,  off);
            int   oi = __shfl_down_sync(0xffffffffu, bi, off);
            if (ov > v || (ov == v && oi < bi)) { v = ov; bi = oi; }
        }
        if (tid == 0) s_idx = bi;
    }
    __syncthreads();
    const int idx = s_idx;

    if (tid < HW) {
        const float A0 = fin[idx][1];
        const float A1 = fin[idx][2];
        float pr0 = fin[tid][3] + A0 + __ldg(bias + 0);
        float pr1 = fin[tid][4] + A1 + __ldg(bias + 1);
        pr0 = fmaxf(pr0, 0.f);
        pr1 = fmaxf(pr1, 0.f);
        if (tid == idx) { pr0 = 0.f; pr1 = 0.f; }

        const float ri = (float)(tid / SIDE - idx / SIDE) * (1.f / (float)SIDE);
        const float rj = (float)(tid % SIDE - idx % SIDE) * (1.f / (float)SIDE);
        const float rd = sqrtf(ri * ri + rj * rj);
        const float ang = (atan2f(rj, ri) * (1.f / 3.14159265358979323846f) + 1.f) * 0.5f;

        float dl = pr0 - rd; dl *= dl;
        float g  = pr1 - ang;
        if (g < 0.f) g += 1.f;
        gaps[tid] = g;
        dls[tid]  = dl;
    }
    __syncthreads();

    if (tid < 32) {
        float t = (tid < HW) ? gaps[tid] : 0.f;
        if (tid + 32 < HW) t += gaps[tid + 32];
        #pragma unroll
        for (int off = 16; off > 0; off >>= 1)
            t += __shfl_down_sync(0xffffffffu, t, off);
        if (tid == 0) s_gmean = t * (1.f / (float)HW);
    }
    __syncthreads();

    if (tid < HW) {
        float g = gaps[tid] - s_gmean;
        out[n * HW + tid] = dls[tid] + g * g;
    }
}

extern "C" void kernel_launch(void* const* d_in, const int* in_sizes, int n_in,
                              void* d_out, int out_size)
{
    const float* x    = (const float*)d_in[0];
    const float* Wlin = (const float*)d_in[1];
    const float* b    = (const float*)d_in[2];
    float*       out  = (float*)d_out;

    const int N = in_sizes[0] / (CC * HW);   // 256

    float* scratch = nullptr;
    cudaGetSymbolAddress((void**)&scratch, g_scratch);

    rpcp_partial_kernel<<<N * SPLIT, NTHR>>>(x, Wlin, scratch);
    rpcp_final_kernel<<<N, 256>>>(scratch, b, out);
}

// round 14
// speedup vs baseline: 1.2797x; 1.2797x over previous
#include <cuda_runtime.h>
#include <cuda_bf16.h>
#include <cstdint>

#define CC      2048
#define HW      49
#define SIDE    7
#define CGROUPS 8
#define NTHR    512
#define SPLIT   16
#define CHC     (CC / SPLIT)      // 128 channels per CTA
#define NMAX    256

// scratch: [u][p][5] = {sum, a0, a1, d0, d1}
__device__ float g_scratch[NMAX * SPLIT * HW * 5];

// ------- K1: streaming partial, 5 accs, reg-lean, occ-3 -------
__global__ __launch_bounds__(NTHR, 3)
void rpcp_partial_kernel(const float* __restrict__ x,
                         const float* __restrict__ Wlin,
                         float* __restrict__ scratch)
{
    __shared__ float4 wsh[CHC];               // {W1_0, W1_1, W2_0, W2_1}: 2 KB
    __shared__ float  acc[CGROUPS][HW][5];

    const int tid = threadIdx.x;
    const int u   = blockIdx.x;               // unit id
    const int n   = u >> 4;                   // SPLIT = 16
    const int sp  = u & 15;
    const int c0  = sp * CHC;

    for (int c = tid; c < CHC; c += NTHR) {
        const int cc = c0 + c;
        wsh[c] = make_float4(Wlin[cc],             // W1_0
                             Wlin[2 * CC + cc],    // W1_1
                             Wlin[CC + cc],        // W2_0
                             Wlin[3 * CC + cc]);   // W2_1
    }
    __syncthreads();

    const int p  = tid & 63;     // 0..48 active
    const int cg = tid >> 6;     // 0..7

    if (p < HW) {
        float s = 0.f, a0 = 0.f, a1 = 0.f, d0 = 0.f, d1 = 0.f;
        const float* xp = x + (size_t)n * CC * HW + (size_t)c0 * HW + p;

        // 4 rounds x 4 front-batched loads; weights loaded in compute phase
        // (not staged across the batch) to stay under the 42-reg occ-3 cap.
        #pragma unroll
        for (int k = 0; k < 4; k++) {
            float v0 = __ldg(xp + (cg + (k * 4 + 0) * CGROUPS) * HW);
            float v1 = __ldg(xp + (cg + (k * 4 + 1) * CGROUPS) * HW);
            float v2 = __ldg(xp + (cg + (k * 4 + 2) * CGROUPS) * HW);
            float v3 = __ldg(xp + (cg + (k * 4 + 3) * CGROUPS) * HW);

            float4 w;
            w = wsh[cg + (k * 4 + 0) * CGROUPS];
            s += v0; a0 = fmaf(v0, w.x, a0); a1 = fmaf(v0, w.y, a1);
                     d0 = fmaf(v0, w.z, d0); d1 = fmaf(v0, w.w, d1);
            w = wsh[cg + (k * 4 + 1) * CGROUPS];
            s += v1; a0 = fmaf(v1, w.x, a0); a1 = fmaf(v1, w.y, a1);
                     d0 = fmaf(v1, w.z, d0); d1 = fmaf(v1, w.w, d1);
            w = wsh[cg + (k * 4 + 2) * CGROUPS];
            s += v2; a0 = fmaf(v2, w.x, a0); a1 = fmaf(v2, w.y, a1);
                     d0 = fmaf(v2, w.z, d0); d1 = fmaf(v2, w.w, d1);
            w = wsh[cg + (k * 4 + 3) * CGROUPS];
            s += v3; a0 = fmaf(v3, w.x, a0); a1 = fmaf(v3, w.y, a1);
                     d0 = fmaf(v3, w.z, d0); d1 = fmaf(v3, w.w, d1);
        }

        acc[cg][p][0] = s;  acc[cg][p][1] = a0; acc[cg][p][2] = a1;
        acc[cg][p][3] = d0; acc[cg][p][4] = d1;
    }
    __syncthreads();

    if (tid < HW * 5) {
        const int pp = tid / 5, k = tid % 5;
        float t = 0.f;
        #pragma unroll
        for (int g = 0; g < CGROUPS; g++) t += acc[g][pp][k];
        scratch[(u * HW + pp) * 5 + k] = t;
    }
}

// ------- K2: per-image reduce + epilogue (scratch-only, proven) -------
__global__ __launch_bounds__(256, 4)
void rpcp_final_kernel(const float* __restrict__ scratch,
                       const float* __restrict__ bias,
                       float* __restrict__ out)
{
    __shared__ float fin[HW][5];   // {sum, a0, a1, d0, d1}
    __shared__ float gaps[HW];
    __shared__ float dls[HW];
    __shared__ float s_gmean;
    __shared__ int   s_idx;

    const int n   = blockIdx.x;
    const int tid = threadIdx.x;

    if (tid < HW * 5) {
        const int pp = tid / 5, k = tid % 5;
        float t = 0.f;
        #pragma unroll
        for (int g = 0; g < SPLIT; g++)
            t += scratch[(((n << 4) + g) * HW + pp) * 5 + k];
        fin[pp][k] = t;
    }
    __syncthreads();

    // warp argmax over channel-sum (first occurrence on ties)
    if (tid < 32) {
        float v  = fin[tid][0];
        int   bi = tid;
        if (tid + 32 < HW) {
            float v2 = fin[tid + 32][0];
            if (v2 > v) { v = v2; bi = tid + 32; }
        }
        #pragma unroll
        for (int off = 16; off > 0; off >>= 1) {
            float ov = __shfl_down_sync(0xffffffffu, v,  off);
            int   oi = __shfl_down_sync(0xffffffffu, bi, off);
            if (ov > v || (ov == v && oi < bi)) { v = ov; bi = oi; }
        }
        if (tid == 0) s_idx = bi;
    }
    __syncthreads();
    const int idx = s_idx;

    if (tid < HW) {
        const float A0 = fin[idx][1];
        const float A1 = fin[idx][2];
        float pr0 = fin[tid][3] + A0 + __ldg(bias + 0);
        float pr1 = fin[tid][4] + A1 + __ldg(bias + 1);
        pr0 = fmaxf(pr0, 0.f);
        pr1 = fmaxf(pr1, 0.f);
        if (tid == idx) { pr0 = 0.f; pr1 = 0.f; }

        const float ri = (float)(tid / SIDE - idx / SIDE) * (1.f / (float)SIDE);
        const float rj = (float)(tid % SIDE - idx % SIDE) * (1.f / (float)SIDE);
        const float rd = sqrtf(ri * ri + rj * rj);
        const float ang = (atan2f(rj, ri) * (1.f / 3.14159265358979323846f) + 1.f) * 0.5f;

        float dl = pr0 - rd; dl *= dl;
        float g  = pr1 - ang;
        if (g < 0.f) g += 1.f;
        gaps[tid] = g;
        dls[tid]  = dl;
    }
    __syncthreads();

    if (tid < 32) {
        float t = (tid < HW) ? gaps[tid] : 0.f;
        if (tid + 32 < HW) t += gaps[tid + 32];
        #pragma unroll
        for (int off = 16; off > 0; off >>= 1)
            t += __shfl_down_sync(0xffffffffu, t, off);
        if (tid == 0) s_gmean = t * (1.f / (float)HW);
    }
    __syncthreads();

    if (tid < HW) {
        float g = gaps[tid] - s_gmean;
        out[n * HW + tid] = dls[tid] + g * g;
    }
}

extern "C" void kernel_launch(void* const* d_in, const int* in_sizes, int n_in,
                              void* d_out, int out_size)
{
    const float* x    = (const float*)d_in[0];
    const float* Wlin = (const float*)d_in[1];
    const float* b    = (const float*)d_in[2];
    float*       out  = (float*)d_out;

    const int N = in_sizes[0] / (CC * HW);   // 256

    float* scratch = nullptr;
    cudaGetSymbolAddress((void**)&scratch, g_scratch);

    rpcp_partial_kernel<<<N * SPLIT, NTHR>>>(x, Wlin, scratch);
    rpcp_final_kernel<<<N, 256>>>(scratch, b, out);
}